// round 7
// baseline (speedup 1.0000x reference)
#include <cuda_runtime.h>
#include <cuda_fp16.h>

// Problem constants
#define BB   4
#define CC   192
#define C3   576
#define HGT  256
#define WID  256
#define HWS  65536
#define NH   4
#define DD   48
#define NCHUNK 32
#define NPART (NCHUNK * 8)    // 256 split-K partial slots

// Scratch (device globals)
__device__ float g_qkv[(size_t)BB * C3 * HWS];          // 1x1 conv output (q,k,v)
__device__ float g_dwv[(size_t)BB * 192 * HWS];         // dwconv output, v only
__device__ float g_sqf[16 * NCHUNK * 96];               // fused sumsq partials
__device__ float g_sq [BB * 2 * CC];                    // ||q||^2, ||k||^2
__device__ float g_part[(size_t)NPART * BB * NH * DD * DD];
__device__ float g_w2 [BB * CC * CC];

// ---------------------------------------------------------------------------
__device__ __forceinline__ unsigned f2tf32(float f) {
    unsigned u;
    asm("cvt.rna.tf32.f32 %0, %1;" : "=r"(u) : "f"(f));
    return u;
}

__device__ __forceinline__ unsigned pack_h2(float lo, float hi) {
    __half2 h = __halves2half2(__float2half_rn(lo), __float2half_rn(hi));
    return *(unsigned*)&h;
}

__device__ __forceinline__ void mma_tf32(float c[4], const unsigned a[4], const unsigned b[2]) {
    asm volatile(
        "mma.sync.aligned.m16n8k8.row.col.f32.tf32.tf32.f32 "
        "{%0,%1,%2,%3}, {%4,%5,%6,%7}, {%8,%9}, {%0,%1,%2,%3};"
        : "+f"(c[0]), "+f"(c[1]), "+f"(c[2]), "+f"(c[3])
        : "r"(a[0]), "r"(a[1]), "r"(a[2]), "r"(a[3]), "r"(b[0]), "r"(b[1]));
}

__device__ __forceinline__ void mma_fp16(float c[4], const unsigned a[4], const unsigned b[2]) {
    asm volatile(
        "mma.sync.aligned.m16n8k16.row.col.f32.f16.f16.f32 "
        "{%0,%1,%2,%3}, {%4,%5,%6,%7}, {%8,%9}, {%0,%1,%2,%3};"
        : "+f"(c[0]), "+f"(c[1]), "+f"(c[2]), "+f"(c[3])
        : "r"(a[0]), "r"(a[1]), "r"(a[2]), "r"(a[3]), "r"(b[0]), "r"(b[1]));
}

// no-op kernel: shifts subsequent launches into ncu's profiled slot
__global__ void noop_kernel() {}

// ---------------------------------------------------------------------------
// fp16 tensor-core GEMM (pipelined): C[M,N] = A[M,K] @ B[K,N], batch grid.z.
// BM=64, BN=256, BK=16 (one m16n8k16 step), 256 threads, 8 warps of 32x64.
// ---------------------------------------------------------------------------
__global__ __launch_bounds__(256, 2) void gemm_fp16_kernel(
    const float* __restrict__ A, const float* __restrict__ B, float* __restrict__ C,
    int M, int N, int K, long sA, long sB, long sC)
{
    __shared__ unsigned Ap[2][8][64 + 4];
    __shared__ unsigned Bp[2][8][256 + 4];

    const float* Ab = A + (long)blockIdx.z * sA;
    const float* Bb = B + (long)blockIdx.z * sB;
    float*       Cb = C + (long)blockIdx.z * sC;

    const int m0 = blockIdx.x * 64;
    const int n0 = blockIdx.y * 256;
    const int t    = threadIdx.x;
    const int lane = t & 31;
    const int wid  = t >> 5;
    const int wm   = (wid & 1) * 32;
    const int wn   = (wid >> 1) * 64;
    const int g    = lane >> 2;
    const int tg   = lane & 3;

    float acc[2][8][4];
    #pragma unroll
    for (int mt = 0; mt < 2; mt++)
        #pragma unroll
        for (int nt = 0; nt < 8; nt++)
            #pragma unroll
            for (int i = 0; i < 4; i++) acc[mt][nt][i] = 0.f;

    const int am  = t >> 2;
    const int ak  = (t & 3) << 2;
    const int ak2 = ak >> 1;
    const int bn4 = (t & 63) << 2;
    const int bk2 = (t >> 6) << 1;

    const float* apt = Ab + (long)(m0 + am) * K + ak;
    const float* bpt = Bb + (long)(bk2 * 2) * N + n0 + bn4;

    float4 pa;
    float4 pb[4];

    pa = *(const float4*)(apt);
    #pragma unroll
    for (int i = 0; i < 4; i++)
        pb[i] = *(const float4*)(bpt + (long)i * N);

    {
        Ap[0][ak2 + 0][am] = pack_h2(pa.x, pa.y);
        Ap[0][ak2 + 1][am] = pack_h2(pa.z, pa.w);
        uint4 u0, u1;
        u0.x = pack_h2(pb[0].x, pb[1].x); u0.y = pack_h2(pb[0].y, pb[1].y);
        u0.z = pack_h2(pb[0].z, pb[1].z); u0.w = pack_h2(pb[0].w, pb[1].w);
        u1.x = pack_h2(pb[2].x, pb[3].x); u1.y = pack_h2(pb[2].y, pb[3].y);
        u1.z = pack_h2(pb[2].z, pb[3].z); u1.w = pack_h2(pb[2].w, pb[3].w);
        *(uint4*)&Bp[0][bk2][bn4]     = u0;
        *(uint4*)&Bp[0][bk2 + 1][bn4] = u1;
    }
    __syncthreads();

    const int NT = K >> 4;
    for (int kt = 0; kt < NT; kt++) {
        const int cur = kt & 1;
        const int nxt = cur ^ 1;

        if (kt + 1 < NT) {
            const float* ap = apt + (kt + 1) * 16;
            const float* bp = bpt + (long)(kt + 1) * 16 * N;
            pa = *(const float4*)(ap);
            #pragma unroll
            for (int i = 0; i < 4; i++)
                pb[i] = *(const float4*)(bp + (long)i * N);
        }

        unsigned af[2][4], bf[8][2];
        #pragma unroll
        for (int mt = 0; mt < 2; mt++) {
            int mb = wm + mt * 16 + g;
            af[mt][0] = Ap[cur][tg][mb];
            af[mt][1] = Ap[cur][tg][mb + 8];
            af[mt][2] = Ap[cur][tg + 4][mb];
            af[mt][3] = Ap[cur][tg + 4][mb + 8];
        }
        #pragma unroll
        for (int nt = 0; nt < 8; nt++) {
            int nb = wn + nt * 8 + g;
            bf[nt][0] = Bp[cur][tg][nb];
            bf[nt][1] = Bp[cur][tg + 4][nb];
        }
        #pragma unroll
        for (int mt = 0; mt < 2; mt++)
            #pragma unroll
            for (int nt = 0; nt < 8; nt++)
                mma_fp16(acc[mt][nt], af[mt], bf[nt]);

        if (kt + 1 < NT) {
            Ap[nxt][ak2 + 0][am] = pack_h2(pa.x, pa.y);
            Ap[nxt][ak2 + 1][am] = pack_h2(pa.z, pa.w);
            uint4 u0, u1;
            u0.x = pack_h2(pb[0].x, pb[1].x); u0.y = pack_h2(pb[0].y, pb[1].y);
            u0.z = pack_h2(pb[0].z, pb[1].z); u0.w = pack_h2(pb[0].w, pb[1].w);
            u1.x = pack_h2(pb[2].x, pb[3].x); u1.y = pack_h2(pb[2].y, pb[3].y);
            u1.z = pack_h2(pb[2].z, pb[3].z); u1.w = pack_h2(pb[2].w, pb[3].w);
            *(uint4*)&Bp[nxt][bk2][bn4]     = u0;
            *(uint4*)&Bp[nxt][bk2 + 1][bn4] = u1;
        }
        __syncthreads();
    }

    #pragma unroll
    for (int mt = 0; mt < 2; mt++) {
        #pragma unroll
        for (int nt = 0; nt < 8; nt++) {
            int row = m0 + wm + mt * 16 + g;
            int col = n0 + wn + nt * 8 + 2 * tg;
            float2 v0 = make_float2(acc[mt][nt][0], acc[mt][nt][1]);
            float2 v1 = make_float2(acc[mt][nt][2], acc[mt][nt][3]);
            *(float2*)(Cb + (long)row * N + col)       = v0;
            *(float2*)(Cb + (long)(row + 8) * N + col) = v1;
        }
    }
}

// ---------------------------------------------------------------------------
// Depthwise 3x3 conv, v channels only. 8 outputs/thread, sliding window.
// grid (4, 8, BB*192), block (64,4).
// ---------------------------------------------------------------------------
__global__ __launch_bounds__(256) void dwconv_v_kernel(const float* __restrict__ w)
{
    const int bc = blockIdx.z;          // b*192 + cv
    const int cv = bc % 192;
    const int b  = bc / 192;
    const float* plane = g_qkv + ((size_t)(b * C3 + 384 + cv)) * HWS;
    float*       op    = g_dwv + (size_t)bc * HWS;

    float wr[9];
    #pragma unroll
    for (int i = 0; i < 9; i++) wr[i] = w[(384 + cv) * 9 + i];

    const int x  = blockIdx.x * 64 + threadIdx.x;
    const int yb = blockIdx.y * 32 + threadIdx.y * 8;

    float o[8];
    #pragma unroll
    for (int i = 0; i < 8; i++) o[i] = 0.f;

    #pragma unroll
    for (int i = -1; i <= 8; i++) {
        int r = yb + i;
        float l = 0.f, cvv = 0.f, rv = 0.f;
        if (r >= 0 && r < HGT) {
            const float* row = plane + r * WID;
            cvv = row[x];
            l   = (x > 0)   ? row[x - 1] : 0.f;
            rv  = (x < 255) ? row[x + 1] : 0.f;
        }
        float h0 = wr[0] * l + wr[1] * cvv + wr[2] * rv;
        float h1 = wr[3] * l + wr[4] * cvv + wr[5] * rv;
        float h2 = wr[6] * l + wr[7] * cvv + wr[8] * rv;
        if (i - 1 >= 0 && i - 1 < 8) o[i - 1] += h2;
        if (i     >= 0 && i     < 8) o[i]     += h1;
        if (i + 1 >= 0 && i + 1 < 8) o[i + 1] += h0;
    }

    #pragma unroll
    for (int j = 0; j < 8; j++)
        op[(size_t)(yb + j) * WID + x] = o[j];
}

// ---------------------------------------------------------------------------
// FUSED: dwconv(q,k) + sumsq + split-K Q K^T Gram partials.
// grid (NCHUNK, 16=BB*NH), 256 threads, dynamic smem 99840 B.
// Per chunk = 8 image rows. Per row: Phase A computes dwconv for 96 channels
// (48 q + 48 k) x 256 px into smem (tf32) straight from g_qkv; Phase B runs
// tf32 Gram MMAs over the row. dw(q,k) never touches DRAM.
// ---------------------------------------------------------------------------
#define FQK_SMEM (2 * DD * 260 * 4)   // 99840 bytes

__global__ __launch_bounds__(256, 1) void fused_dwqk_kernel(const float* __restrict__ dww)
{
    extern __shared__ unsigned smem_u[];
    unsigned (*qs)[260] = (unsigned(*)[260])smem_u;
    unsigned (*ks)[260] = (unsigned(*)[260])(smem_u + DD * 260);

    const int chunk = blockIdx.x;      // 0..31
    const int bh    = blockIdx.y;      // 0..15
    const int b  = bh >> 2;
    const int hh = bh & 3;
    const int y0 = chunk * 8;

    const float* qplane = g_qkv + ((size_t)b * C3 + hh * DD) * HWS;
    const float* kplane = g_qkv + ((size_t)b * C3 + 192 + hh * DD) * HWS;

    const int t    = threadIdx.x;
    const int lane = t & 31;
    const int w    = t >> 5;
    const int g    = lane >> 2;
    const int tg   = lane & 3;

    float mmacc[3][6][4];
    #pragma unroll
    for (int mt = 0; mt < 3; mt++)
        #pragma unroll
        for (int nt = 0; nt < 6; nt++)
            #pragma unroll
            for (int i = 0; i < 4; i++) mmacc[mt][nt][i] = 0.f;

    float ssq[6];
    #pragma unroll
    for (int i = 0; i < 6; i++) ssq[i] = 0.f;

    for (int y = y0; y < y0 + 8; y++) {
        // ---- Phase A: dwconv row y for 96 channels -> smem (tf32) ----
        #pragma unroll
        for (int i = 0; i < 6; i++) {
            const int u  = t + i * 256;       // 0..1535 = 96 ch x 16 x-sixteenths
            const int ch = u >> 4;            // 0..95 (0-47: q, 48-95: k)
            const int x0 = (u & 15) << 4;     // 0..240

            const float* plane = (ch < DD) ? (qplane + (size_t)ch * HWS)
                                           : (kplane + (size_t)(ch - DD) * HWS);
            const int wc = (ch < DD) ? (hh * DD + ch) : (192 + hh * DD + (ch - DD));
            const float* wch = dww + wc * 9;

            float acc[16];
            #pragma unroll
            for (int x = 0; x < 16; x++) acc[x] = 0.f;

            #pragma unroll
            for (int dy = -1; dy <= 1; dy++) {
                int r = y + dy;
                if (r >= 0 && r < HGT) {
                    const float* row = plane + (size_t)r * WID;
                    float m[16];
                    #pragma unroll
                    for (int p = 0; p < 4; p++)
                        *(float4*)&m[p * 4] = *(const float4*)(row + x0 + p * 4);
                    float lft = (x0 > 0)   ? row[x0 - 1]  : 0.f;
                    float rgt = (x0 < 240) ? row[x0 + 16] : 0.f;
                    float w0 = wch[(dy + 1) * 3 + 0];
                    float w1 = wch[(dy + 1) * 3 + 1];
                    float w2 = wch[(dy + 1) * 3 + 2];
                    #pragma unroll
                    for (int x = 0; x < 16; x++) {
                        float lv = (x > 0)  ? m[x - 1] : lft;
                        float rv = (x < 15) ? m[x + 1] : rgt;
                        acc[x] += w0 * lv + w1 * m[x] + w2 * rv;
                    }
                }
            }

            float s = 0.f;
            #pragma unroll
            for (int x = 0; x < 16; x++) s += acc[x] * acc[x];
            ssq[i] += s;

            unsigned* dst = (ch < DD) ? &qs[ch][x0] : &ks[ch - DD][x0];
            #pragma unroll
            for (int p = 0; p < 4; p++) {
                uint4 uq;
                uq.x = f2tf32(acc[p * 4 + 0]); uq.y = f2tf32(acc[p * 4 + 1]);
                uq.z = f2tf32(acc[p * 4 + 2]); uq.w = f2tf32(acc[p * 4 + 3]);
                *(uint4*)(dst + p * 4) = uq;
            }
        }
        __syncthreads();

        // ---- Phase B: Gram MMAs over this row (32 slices of 8 px) ----
        #pragma unroll
        for (int s = 0; s < 4; s++) {
            const int s0 = (w * 4 + s) * 8;
            unsigned af[3][4], bf[6][2];
            #pragma unroll
            for (int mt = 0; mt < 3; mt++) {
                int m = mt * 16 + g;
                af[mt][0] = qs[m][s0 + tg];
                af[mt][1] = qs[m + 8][s0 + tg];
                af[mt][2] = qs[m][s0 + tg + 4];
                af[mt][3] = qs[m + 8][s0 + tg + 4];
            }
            #pragma unroll
            for (int nt = 0; nt < 6; nt++) {
                int n = nt * 8 + g;
                bf[nt][0] = ks[n][s0 + tg];
                bf[nt][1] = ks[n][s0 + tg + 4];
            }
            #pragma unroll
            for (int mt = 0; mt < 3; mt++)
                #pragma unroll
                for (int nt = 0; nt < 6; nt++)
                    mma_tf32(mmacc[mt][nt], af[mt], bf[nt]);
        }
        __syncthreads();
    }

    // ---- write Gram partials (slot = chunk*8 + warp; deterministic) ----
    float* dst = g_part + ((size_t)(chunk * 8 + w) * (BB * NH) + bh) * (DD * DD);
    #pragma unroll
    for (int mt = 0; mt < 3; mt++) {
        #pragma unroll
        for (int nt = 0; nt < 6; nt++) {
            int row = mt * 16 + g;
            int col = nt * 8 + 2 * tg;
            *(float2*)(dst + row * DD + col)       = make_float2(mmacc[mt][nt][0], mmacc[mt][nt][1]);
            *(float2*)(dst + (row + 8) * DD + col) = make_float2(mmacc[mt][nt][2], mmacc[mt][nt][3]);
        }
    }

    // ---- sumsq partial reduction via smem reuse ----
    float* sq = (float*)smem_u;   // 96*16 floats
    #pragma unroll
    for (int i = 0; i < 6; i++) {
        int u = t + i * 256;
        sq[(u >> 4) * 16 + (u & 15)] = ssq[i];
    }
    __syncthreads();
    if (t < 96) {
        float v = 0.f;
        #pragma unroll
        for (int j = 0; j < 16; j++) v += sq[t * 16 + j];
        g_sqf[(bh * NCHUNK + chunk) * 96 + t] = v;
    }
}

// ---------------------------------------------------------------------------
// Reduce fused sumsq partials over 32 chunks. grid (16*96), 32 threads.
// ---------------------------------------------------------------------------
__global__ __launch_bounds__(32) void sumsq_reduce2_kernel()
{
    const int idx = blockIdx.x;        // bh*96 + ch
    const int bh = idx / 96;
    const int ch = idx % 96;
    const int b  = bh >> 2;
    const int hh = bh & 3;

    float v = g_sqf[(bh * NCHUNK + threadIdx.x) * 96 + ch];
    #pragma unroll
    for (int off = 16; off > 0; off >>= 1)
        v += __shfl_down_sync(0xffffffffu, v, off);
    if (threadIdx.x == 0) {
        int o = (ch < DD) ? (b * 2 * CC + hh * DD + ch)
                          : (b * 2 * CC + CC + hh * DD + (ch - DD));
        g_sq[o] = v;
    }
}

// ---------------------------------------------------------------------------
// Reduce Gram partials -> scale -> softmax -> W2 = proj_w @ blockdiag(attn).
// ---------------------------------------------------------------------------
__global__ __launch_bounds__(192) void softmax_w2_kernel(
    const float* __restrict__ temp, const float* __restrict__ projw)
{
    const int bh = blockIdx.x;
    const int b  = bh >> 2;
    const int hh = bh & 3;
    const int t  = threadIdx.x;

    __shared__ float S[DD][DD];
    __shared__ float nq[DD], nk[DD];

    for (int i = t; i < DD * DD; i += 192) {
        float s = 0.f;
        #pragma unroll 8
        for (int ch = 0; ch < NPART; ch++)
            s += g_part[((size_t)ch * (BB * NH) + bh) * (DD * DD) + i];
        S[i / DD][i % DD] = s;
    }
    if (t < DD) {
        nq[t] = fmaxf(sqrtf(g_sq[b * 2 * CC + hh * DD + t]),      1e-12f);
        nk[t] = fmaxf(sqrtf(g_sq[b * 2 * CC + CC + hh * DD + t]), 1e-12f);
    }
    __syncthreads();

    const float tmp = temp[hh];
    for (int i = t; i < DD * DD; i += 192) {
        int d = i / DD, e = i % DD;
        S[d][e] = S[d][e] * tmp / (nq[d] * nk[e]);
    }
    __syncthreads();

    if (t < DD) {
        float mx = -1e30f;
        #pragma unroll
        for (int e = 0; e < DD; e++) mx = fmaxf(mx, S[t][e]);
        float sum = 0.f;
        #pragma unroll
        for (int e = 0; e < DD; e++) { float v = expf(S[t][e] - mx); S[t][e] = v; sum += v; }
        float inv = 1.f / sum;
        #pragma unroll
        for (int e = 0; e < DD; e++) S[t][e] *= inv;
    }
    __syncthreads();

    const int o = t;
    float pr[DD];
    #pragma unroll
    for (int d = 0; d < DD; d++) pr[d] = projw[o * CC + hh * DD + d];
    #pragma unroll 4
    for (int e = 0; e < DD; e++) {
        float s = 0.f;
        #pragma unroll
        for (int d = 0; d < DD; d++) s += pr[d] * S[d][e];
        g_w2[((size_t)b * CC + o) * CC + hh * DD + e] = s;
    }
}

// ---------------------------------------------------------------------------
extern "C" void kernel_launch(void* const* d_in, const int* in_sizes, int n_in,
                              void* d_out, int out_size)
{
    const float* x      = (const float*)d_in[0];
    const float* qkv_w  = (const float*)d_in[1];
    const float* dw_w   = (const float*)d_in[2];
    const float* temp   = (const float*)d_in[3];
    const float* proj_w = (const float*)d_in[4];
    float* out = (float*)d_out;

    float *qkv_buf, *dwv_buf, *w2_buf;
    cudaGetSymbolAddress((void**)&qkv_buf, g_qkv);
    cudaGetSymbolAddress((void**)&dwv_buf, g_dwv);
    cudaGetSymbolAddress((void**)&w2_buf,  g_w2);

    cudaFuncSetAttribute(fused_dwqk_kernel,
                         cudaFuncAttributeMaxDynamicSharedMemorySize, FQK_SMEM);

    // 3 no-ops so the 4th launch (gemm1) lands in ncu's profiled slot
    noop_kernel<<<1, 32>>>();
    noop_kernel<<<1, 32>>>();
    noop_kernel<<<1, 32>>>();

    // 1) qkv 1x1 conv (fp16 tensor cores)  <-- should be profiled this round
    gemm_fp16_kernel<<<dim3(C3 / 64, HWS / 256, BB), 256>>>(
        qkv_w, x, qkv_buf, C3, HWS, CC,
        0L, (long)CC * HWS, (long)C3 * HWS);

    // 2) depthwise 3x3 for v only
    dwconv_v_kernel<<<dim3(4, 8, BB * 192), dim3(64, 4)>>>(dw_w);

    // 3) FUSED dwconv(q,k) + sumsq + Q K^T partials
    fused_dwqk_kernel<<<dim3(NCHUNK, BB * NH), 256, FQK_SMEM>>>(dw_w);

    // 4) finish ||q||^2, ||k||^2
    sumsq_reduce2_kernel<<<16 * 96, 32>>>();

    // 5) reduce + scale + softmax + W2
    softmax_w2_kernel<<<BB * NH, 192>>>(temp, proj_w);

    // 6) fused (attn @ v) + proj
    gemm_fp16_kernel<<<dim3(CC / 64, HWS / 256, BB), 256>>>(
        w2_buf, dwv_buf, out, CC, HWS, CC,
        (long)CC * CC, (long)192 * HWS, (long)CC * HWS);
}

// round 8
// speedup vs baseline: 1.1533x; 1.1533x over previous
#include <cuda_runtime.h>
#include <cuda_fp16.h>

// Problem constants
#define BB   4
#define CC   192
#define C3   576
#define HGT  256
#define WID  256
#define HWS  65536
#define NH   4
#define DD   48
#define NCHUNK 32
#define CHL  (HWS / NCHUNK)   // 2048
#define NPART (NCHUNK * 8)    // 256 split-K partial slots

// Scratch (device globals)
__device__ float g_qkv[(size_t)BB * C3 * HWS];
__device__ float g_dw [(size_t)BB * C3 * HWS];
__device__ float g_sqp[BB * C3][32];
__device__ float g_sq [BB * 2 * CC];
__device__ float g_part[(size_t)NPART * BB * NH * DD * DD];
__device__ float g_w2 [BB * CC * CC];

// ---------------------------------------------------------------------------
__device__ __forceinline__ unsigned f2tf32(float f) {
    unsigned u;
    asm("cvt.rna.tf32.f32 %0, %1;" : "=r"(u) : "f"(f));
    return u;
}

__device__ __forceinline__ unsigned pack_h2(float lo, float hi) {
    __half2 h = __halves2half2(__float2half_rn(lo), __float2half_rn(hi));
    return *(unsigned*)&h;
}

__device__ __forceinline__ void mma_tf32(float c[4], const unsigned a[4], const unsigned b[2]) {
    asm volatile(
        "mma.sync.aligned.m16n8k8.row.col.f32.tf32.tf32.f32 "
        "{%0,%1,%2,%3}, {%4,%5,%6,%7}, {%8,%9}, {%0,%1,%2,%3};"
        : "+f"(c[0]), "+f"(c[1]), "+f"(c[2]), "+f"(c[3])
        : "r"(a[0]), "r"(a[1]), "r"(a[2]), "r"(a[3]), "r"(b[0]), "r"(b[1]));
}

__device__ __forceinline__ void mma_fp16(float c[4], const unsigned a[4], const unsigned b[2]) {
    asm volatile(
        "mma.sync.aligned.m16n8k16.row.col.f32.f16.f16.f32 "
        "{%0,%1,%2,%3}, {%4,%5,%6,%7}, {%8,%9}, {%0,%1,%2,%3};"
        : "+f"(c[0]), "+f"(c[1]), "+f"(c[2]), "+f"(c[3])
        : "r"(a[0]), "r"(a[1]), "r"(a[2]), "r"(a[3]), "r"(b[0]), "r"(b[1]));
}

// no-op kernel: shifts subsequent launches into ncu's profiled slot
__global__ void noop_kernel() {}

// ---------------------------------------------------------------------------
// fp16 tensor-core GEMM (pipelined): C[M,N] = A[M,K] @ B[K,N], batch grid.z.
// BM=64, BN=256, BK=16, 256 threads. Smem strides ≡ 8 (mod 32) words so
// fragment LDS banks = (8*tg + g + const) & 31 -> conflict-free.
// ---------------------------------------------------------------------------
__global__ __launch_bounds__(256, 2) void gemm_fp16_kernel(
    const float* __restrict__ A, const float* __restrict__ B, float* __restrict__ C,
    int M, int N, int K, long sA, long sB, long sC)
{
    __shared__ unsigned Ap[2][8][64 + 8];    // stride 72 words
    __shared__ unsigned Bp[2][8][256 + 8];   // stride 264 words

    const float* Ab = A + (long)blockIdx.z * sA;
    const float* Bb = B + (long)blockIdx.z * sB;
    float*       Cb = C + (long)blockIdx.z * sC;

    const int m0 = blockIdx.x * 64;
    const int n0 = blockIdx.y * 256;
    const int t    = threadIdx.x;
    const int lane = t & 31;
    const int wid  = t >> 5;
    const int wm   = (wid & 1) * 32;
    const int wn   = (wid >> 1) * 64;
    const int g    = lane >> 2;
    const int tg   = lane & 3;

    float acc[2][8][4];
    #pragma unroll
    for (int mt = 0; mt < 2; mt++)
        #pragma unroll
        for (int nt = 0; nt < 8; nt++)
            #pragma unroll
            for (int i = 0; i < 4; i++) acc[mt][nt][i] = 0.f;

    const int am  = t >> 2;
    const int ak  = (t & 3) << 2;
    const int ak2 = ak >> 1;
    const int bn4 = (t & 63) << 2;
    const int bk2 = (t >> 6) << 1;

    const float* apt = Ab + (long)(m0 + am) * K + ak;
    const float* bpt = Bb + (long)(bk2 * 2) * N + n0 + bn4;

    float4 pa;
    float4 pb[4];

    pa = *(const float4*)(apt);
    #pragma unroll
    for (int i = 0; i < 4; i++)
        pb[i] = *(const float4*)(bpt + (long)i * N);

    {
        Ap[0][ak2 + 0][am] = pack_h2(pa.x, pa.y);
        Ap[0][ak2 + 1][am] = pack_h2(pa.z, pa.w);
        uint4 u0, u1;
        u0.x = pack_h2(pb[0].x, pb[1].x); u0.y = pack_h2(pb[0].y, pb[1].y);
        u0.z = pack_h2(pb[0].z, pb[1].z); u0.w = pack_h2(pb[0].w, pb[1].w);
        u1.x = pack_h2(pb[2].x, pb[3].x); u1.y = pack_h2(pb[2].y, pb[3].y);
        u1.z = pack_h2(pb[2].z, pb[3].z); u1.w = pack_h2(pb[2].w, pb[3].w);
        *(uint4*)&Bp[0][bk2][bn4]     = u0;
        *(uint4*)&Bp[0][bk2 + 1][bn4] = u1;
    }
    __syncthreads();

    const int NT = K >> 4;
    for (int kt = 0; kt < NT; kt++) {
        const int cur = kt & 1;
        const int nxt = cur ^ 1;

        if (kt + 1 < NT) {
            const float* ap = apt + (kt + 1) * 16;
            const float* bp = bpt + (long)(kt + 1) * 16 * N;
            pa = *(const float4*)(ap);
            #pragma unroll
            for (int i = 0; i < 4; i++)
                pb[i] = *(const float4*)(bp + (long)i * N);
        }

        unsigned af[2][4], bf[8][2];
        #pragma unroll
        for (int mt = 0; mt < 2; mt++) {
            int mb = wm + mt * 16 + g;
            af[mt][0] = Ap[cur][tg][mb];
            af[mt][1] = Ap[cur][tg][mb + 8];
            af[mt][2] = Ap[cur][tg + 4][mb];
            af[mt][3] = Ap[cur][tg + 4][mb + 8];
        }
        #pragma unroll
        for (int nt = 0; nt < 8; nt++) {
            int nb = wn + nt * 8 + g;
            bf[nt][0] = Bp[cur][tg][nb];
            bf[nt][1] = Bp[cur][tg + 4][nb];
        }
        #pragma unroll
        for (int mt = 0; mt < 2; mt++)
            #pragma unroll
            for (int nt = 0; nt < 8; nt++)
                mma_fp16(acc[mt][nt], af[mt], bf[nt]);

        if (kt + 1 < NT) {
            Ap[nxt][ak2 + 0][am] = pack_h2(pa.x, pa.y);
            Ap[nxt][ak2 + 1][am] = pack_h2(pa.z, pa.w);
            uint4 u0, u1;
            u0.x = pack_h2(pb[0].x, pb[1].x); u0.y = pack_h2(pb[0].y, pb[1].y);
            u0.z = pack_h2(pb[0].z, pb[1].z); u0.w = pack_h2(pb[0].w, pb[1].w);
            u1.x = pack_h2(pb[2].x, pb[3].x); u1.y = pack_h2(pb[2].y, pb[3].y);
            u1.z = pack_h2(pb[2].z, pb[3].z); u1.w = pack_h2(pb[2].w, pb[3].w);
            *(uint4*)&Bp[nxt][bk2][bn4]     = u0;
            *(uint4*)&Bp[nxt][bk2 + 1][bn4] = u1;
        }
        __syncthreads();
    }

    #pragma unroll
    for (int mt = 0; mt < 2; mt++) {
        #pragma unroll
        for (int nt = 0; nt < 8; nt++) {
            int row = m0 + wm + mt * 16 + g;
            int col = n0 + wn + nt * 8 + 2 * tg;
            float2 v0 = make_float2(acc[mt][nt][0], acc[mt][nt][1]);
            float2 v1 = make_float2(acc[mt][nt][2], acc[mt][nt][3]);
            *(float2*)(Cb + (long)row * N + col)       = v0;
            *(float2*)(Cb + (long)(row + 8) * N + col) = v1;
        }
    }
}

// ---------------------------------------------------------------------------
// Depthwise 3x3 conv (R6 version): 8 outputs/thread, fused sumsq partials.
// grid (4, 8, BB*C3), block (64,4).
// ---------------------------------------------------------------------------
__global__ __launch_bounds__(256) void dwconv_kernel(const float* __restrict__ w)
{
    const int bc = blockIdx.z;
    const int c  = bc % C3;
    const float* plane = g_qkv + (size_t)bc * HWS;
    float*       op    = g_dw  + (size_t)bc * HWS;

    float wr[9];
    #pragma unroll
    for (int i = 0; i < 9; i++) wr[i] = w[c * 9 + i];

    const int x  = blockIdx.x * 64 + threadIdx.x;
    const int yb = blockIdx.y * 32 + threadIdx.y * 8;

    float o[8];
    #pragma unroll
    for (int i = 0; i < 8; i++) o[i] = 0.f;

    #pragma unroll
    for (int i = -1; i <= 8; i++) {
        int r = yb + i;
        float l = 0.f, cv = 0.f, rv = 0.f;
        if (r >= 0 && r < HGT) {
            const float* row = plane + r * WID;
            cv = row[x];
            l  = (x > 0)   ? row[x - 1] : 0.f;
            rv = (x < 255) ? row[x + 1] : 0.f;
        }
        float h0 = wr[0] * l + wr[1] * cv + wr[2] * rv;
        float h1 = wr[3] * l + wr[4] * cv + wr[5] * rv;
        float h2 = wr[6] * l + wr[7] * cv + wr[8] * rv;
        if (i - 1 >= 0 && i - 1 < 8) o[i - 1] += h2;
        if (i     >= 0 && i     < 8) o[i]     += h1;
        if (i + 1 >= 0 && i + 1 < 8) o[i + 1] += h0;
    }

    float ss = 0.f;
    #pragma unroll
    for (int j = 0; j < 8; j++) {
        op[(size_t)(yb + j) * WID + x] = o[j];
        ss += o[j] * o[j];
    }

    if (c < 2 * CC) {
        __shared__ float red[256];
        const int t = threadIdx.y * 64 + threadIdx.x;
        red[t] = ss;
        __syncthreads();
        #pragma unroll
        for (int off = 128; off > 0; off >>= 1) {
            if (t < off) red[t] += red[t + off];
            __syncthreads();
        }
        if (t == 0) g_sqp[bc][blockIdx.y * 4 + blockIdx.x] = red[0];
    }
}

// ---------------------------------------------------------------------------
__global__ __launch_bounds__(32) void sumsq_reduce_kernel()
{
    const int idx = blockIdx.x;             // b * 384 + c
    const int b = idx / (2 * CC);
    const int c = idx % (2 * CC);
    float v = g_sqp[b * C3 + c][threadIdx.x];
    #pragma unroll
    for (int off = 16; off > 0; off >>= 1)
        v += __shfl_down_sync(0xffffffffu, v, off);
    if (threadIdx.x == 0) g_sq[idx] = v;
}

// ---------------------------------------------------------------------------
// Split-K partials of S = Q @ K^T per (b,h) with tf32 MMA (R6 version).
// ---------------------------------------------------------------------------
__global__ __launch_bounds__(256) void qk_partial_kernel()
{
    const int chunk = blockIdx.x;
    const int bh    = blockIdx.y;
    const int b  = bh >> 2;
    const int hh = bh & 3;

    const float* qb = g_dw + ((size_t)b * C3 + hh * DD) * HWS + (size_t)chunk * CHL;
    const float* kb = qb + (size_t)CC * HWS;

    __shared__ unsigned qs[DD][68];
    __shared__ unsigned ks[DD][68];

    const int t    = threadIdx.x;
    const int lane = t & 31;
    const int w    = t >> 5;
    const int g    = lane >> 2;
    const int tg   = lane & 3;
    const int s0   = w * 8;

    float acc[3][6][4];
    #pragma unroll
    for (int mt = 0; mt < 3; mt++)
        #pragma unroll
        for (int nt = 0; nt < 6; nt++)
            #pragma unroll
            for (int i = 0; i < 4; i++) acc[mt][nt][i] = 0.f;

    for (int n0 = 0; n0 < CHL; n0 += 64) {
        #pragma unroll
        for (int i = 0; i < 3; i++) {
            int f  = t + i * 256;
            int cc = f >> 4;
            int c4 = (f & 15) << 2;
            float4 qv = *(const float4*)(qb + (size_t)cc * HWS + n0 + c4);
            float4 kv = *(const float4*)(kb + (size_t)cc * HWS + n0 + c4);
            uint4 uq, uk;
            uq.x = f2tf32(qv.x); uq.y = f2tf32(qv.y); uq.z = f2tf32(qv.z); uq.w = f2tf32(qv.w);
            uk.x = f2tf32(kv.x); uk.y = f2tf32(kv.y); uk.z = f2tf32(kv.z); uk.w = f2tf32(kv.w);
            *(uint4*)&qs[cc][c4] = uq;
            *(uint4*)&ks[cc][c4] = uk;
        }
        __syncthreads();

        unsigned af[3][4], bf[6][2];
        #pragma unroll
        for (int mt = 0; mt < 3; mt++) {
            int m = mt * 16 + g;
            af[mt][0] = qs[m][s0 + tg];
            af[mt][1] = qs[m + 8][s0 + tg];
            af[mt][2] = qs[m][s0 + tg + 4];
            af[mt][3] = qs[m + 8][s0 + tg + 4];
        }
        #pragma unroll
        for (int nt = 0; nt < 6; nt++) {
            int n = nt * 8 + g;
            bf[nt][0] = ks[n][s0 + tg];
            bf[nt][1] = ks[n][s0 + tg + 4];
        }
        #pragma unroll
        for (int mt = 0; mt < 3; mt++)
            #pragma unroll
            for (int nt = 0; nt < 6; nt++)
                mma_tf32(acc[mt][nt], af[mt], bf[nt]);
        __syncthreads();
    }

    float* dst = g_part + ((size_t)(chunk * 8 + w) * (BB * NH) + bh) * (DD * DD);
    #pragma unroll
    for (int mt = 0; mt < 3; mt++) {
        #pragma unroll
        for (int nt = 0; nt < 6; nt++) {
            int row = mt * 16 + g;
            int col = nt * 8 + 2 * tg;
            *(float2*)(dst + row * DD + col)       = make_float2(acc[mt][nt][0], acc[mt][nt][1]);
            *(float2*)(dst + (row + 8) * DD + col) = make_float2(acc[mt][nt][2], acc[mt][nt][3]);
        }
    }
}

// ---------------------------------------------------------------------------
// Reduce partials -> scale -> softmax -> W2 = proj_w @ blockdiag(attn).
// ---------------------------------------------------------------------------
__global__ __launch_bounds__(192) void softmax_w2_kernel(
    const float* __restrict__ temp, const float* __restrict__ projw)
{
    const int bh = blockIdx.x;
    const int b  = bh >> 2;
    const int hh = bh & 3;
    const int t  = threadIdx.x;

    __shared__ float S[DD][DD];
    __shared__ float nq[DD], nk[DD];

    for (int i = t; i < DD * DD; i += 192) {
        float s = 0.f;
        #pragma unroll 8
        for (int ch = 0; ch < NPART; ch++)
            s += g_part[((size_t)ch * (BB * NH) + bh) * (DD * DD) + i];
        S[i / DD][i % DD] = s;
    }
    if (t < DD) {
        nq[t] = fmaxf(sqrtf(g_sq[b * 2 * CC + hh * DD + t]),      1e-12f);
        nk[t] = fmaxf(sqrtf(g_sq[b * 2 * CC + CC + hh * DD + t]), 1e-12f);
    }
    __syncthreads();

    const float tmp = temp[hh];
    for (int i = t; i < DD * DD; i += 192) {
        int d = i / DD, e = i % DD;
        S[d][e] = S[d][e] * tmp / (nq[d] * nk[e]);
    }
    __syncthreads();

    if (t < DD) {
        float mx = -1e30f;
        #pragma unroll
        for (int e = 0; e < DD; e++) mx = fmaxf(mx, S[t][e]);
        float sum = 0.f;
        #pragma unroll
        for (int e = 0; e < DD; e++) { float v = expf(S[t][e] - mx); S[t][e] = v; sum += v; }
        float inv = 1.f / sum;
        #pragma unroll
        for (int e = 0; e < DD; e++) S[t][e] *= inv;
    }
    __syncthreads();

    const int o = t;
    float pr[DD];
    #pragma unroll
    for (int d = 0; d < DD; d++) pr[d] = projw[o * CC + hh * DD + d];
    #pragma unroll 4
    for (int e = 0; e < DD; e++) {
        float s = 0.f;
        #pragma unroll
        for (int d = 0; d < DD; d++) s += pr[d] * S[d][e];
        g_w2[((size_t)b * CC + o) * CC + hh * DD + e] = s;
    }
}

// ---------------------------------------------------------------------------
extern "C" void kernel_launch(void* const* d_in, const int* in_sizes, int n_in,
                              void* d_out, int out_size)
{
    const float* x      = (const float*)d_in[0];
    const float* qkv_w  = (const float*)d_in[1];
    const float* dw_w   = (const float*)d_in[2];
    const float* temp   = (const float*)d_in[3];
    const float* proj_w = (const float*)d_in[4];
    float* out = (float*)d_out;

    float *qkv_buf, *dw_buf, *w2_buf;
    cudaGetSymbolAddress((void**)&qkv_buf, g_qkv);
    cudaGetSymbolAddress((void**)&dw_buf,  g_dw);
    cudaGetSymbolAddress((void**)&w2_buf,  g_w2);

    // 3 no-ops so the 4th launch (gemm1) lands in ncu's profiled slot
    noop_kernel<<<1, 32>>>();
    noop_kernel<<<1, 32>>>();
    noop_kernel<<<1, 32>>>();

    // 1) qkv 1x1 conv (fp16 tensor cores, conflict-free smem)
    gemm_fp16_kernel<<<dim3(C3 / 64, HWS / 256, BB), 256>>>(
        qkv_w, x, qkv_buf, C3, HWS, CC,
        0L, (long)CC * HWS, (long)C3 * HWS);

    // 2) depthwise 3x3 (+ fused sumsq partials)
    dwconv_kernel<<<dim3(4, 8, BB * C3), dim3(64, 4)>>>(dw_w);

    // 3) finish ||q||^2, ||k||^2
    sumsq_reduce_kernel<<<BB * 2 * CC, 32>>>();

    // 4) split-K S = Q K^T partials (tf32 MMA)
    qk_partial_kernel<<<dim3(NCHUNK, BB * NH), 256>>>();

    // 5) reduce + scale + softmax + W2
    softmax_w2_kernel<<<BB * NH, 192>>>(temp, proj_w);

    // 6) fused (attn @ v) + proj (fp16 tensor cores, conflict-free smem)
    gemm_fp16_kernel<<<dim3(CC / 64, HWS / 256, BB), 256>>>(
        w2_buf, g_dw ? (dw_buf + (size_t)2 * CC * HWS) : dw_buf, out, CC, HWS, CC,
        (long)CC * CC, (long)C3 * HWS, (long)CC * HWS);
}

// round 9
// speedup vs baseline: 1.4124x; 1.2247x over previous
#include <cuda_runtime.h>
#include <cuda_fp16.h>

// Problem constants
#define BB   4
#define CC   192
#define C3   576
#define HGT  256
#define WID  256
#define HWS  65536
#define NH   4
#define DD   48
#define NCHUNK 32
#define CHL  (HWS / NCHUNK)   // 2048
#define NPART (NCHUNK * 8)    // 256 split-K partial slots

// Scratch (device globals)
__device__ __half g_qkvh[(size_t)BB * C3 * HWS];  // 1x1 conv output (fp16)
__device__ __half g_dwh [(size_t)BB * C3 * HWS];  // dwconv output (fp16)
__device__ float  g_sqp[BB * C3][32];
__device__ float  g_sq [BB * 2 * CC];
__device__ float  g_part[(size_t)NPART * BB * NH * DD * DD];
__device__ float  g_S  [16 * DD * DD];            // reduced Gram
__device__ float  g_w2 [BB * CC * CC];

// ---------------------------------------------------------------------------
__device__ __forceinline__ unsigned pack_h2(float lo, float hi) {
    __half2 h = __halves2half2(__float2half_rn(lo), __float2half_rn(hi));
    return *(unsigned*)&h;
}

__device__ __forceinline__ void mma_fp16(float c[4], const unsigned a[4], const unsigned b[2]) {
    asm volatile(
        "mma.sync.aligned.m16n8k16.row.col.f32.f16.f16.f32 "
        "{%0,%1,%2,%3}, {%4,%5,%6,%7}, {%8,%9}, {%0,%1,%2,%3};"
        : "+f"(c[0]), "+f"(c[1]), "+f"(c[2]), "+f"(c[3])
        : "r"(a[0]), "r"(a[1]), "r"(a[2]), "r"(a[3]), "r"(b[0]), "r"(b[1]));
}

// no-op kernel: shifts subsequent launches into ncu's profiled (4th) slot
__global__ void noop_kernel() {}

// ---------------------------------------------------------------------------
// GEMM1: C[M,N](half) = A[M,K](f32) @ B[K,N](f32). batch grid.z.
// BM=64, BN=256, BK=16, 256 threads; conflict-free smem (stride ≡ 8 mod 32).
// ---------------------------------------------------------------------------
__global__ __launch_bounds__(256, 2) void gemm1_kernel(
    const float* __restrict__ A, const float* __restrict__ B, __half* __restrict__ C,
    int M, int N, int K, long sA, long sB, long sC)
{
    __shared__ unsigned Ap[2][8][64 + 8];
    __shared__ unsigned Bp[2][8][256 + 8];

    const float* Ab = A + (long)blockIdx.z * sA;
    const float* Bb = B + (long)blockIdx.z * sB;
    __half*      Cb = C + (long)blockIdx.z * sC;

    const int m0 = blockIdx.x * 64;
    const int n0 = blockIdx.y * 256;
    const int t    = threadIdx.x;
    const int lane = t & 31;
    const int wid  = t >> 5;
    const int wm   = (wid & 1) * 32;
    const int wn   = (wid >> 1) * 64;
    const int g    = lane >> 2;
    const int tg   = lane & 3;

    float acc[2][8][4];
    #pragma unroll
    for (int mt = 0; mt < 2; mt++)
        #pragma unroll
        for (int nt = 0; nt < 8; nt++)
            #pragma unroll
            for (int i = 0; i < 4; i++) acc[mt][nt][i] = 0.f;

    const int am  = t >> 2;
    const int ak  = (t & 3) << 2;
    const int ak2 = ak >> 1;
    const int bn4 = (t & 63) << 2;
    const int bk2 = (t >> 6) << 1;

    const float* apt = Ab + (long)(m0 + am) * K + ak;
    const float* bpt = Bb + (long)(bk2 * 2) * N + n0 + bn4;

    float4 pa;
    float4 pb[4];

    pa = *(const float4*)(apt);
    #pragma unroll
    for (int i = 0; i < 4; i++)
        pb[i] = *(const float4*)(bpt + (long)i * N);

    {
        Ap[0][ak2 + 0][am] = pack_h2(pa.x, pa.y);
        Ap[0][ak2 + 1][am] = pack_h2(pa.z, pa.w);
        uint4 u0, u1;
        u0.x = pack_h2(pb[0].x, pb[1].x); u0.y = pack_h2(pb[0].y, pb[1].y);
        u0.z = pack_h2(pb[0].z, pb[1].z); u0.w = pack_h2(pb[0].w, pb[1].w);
        u1.x = pack_h2(pb[2].x, pb[3].x); u1.y = pack_h2(pb[2].y, pb[3].y);
        u1.z = pack_h2(pb[2].z, pb[3].z); u1.w = pack_h2(pb[2].w, pb[3].w);
        *(uint4*)&Bp[0][bk2][bn4]     = u0;
        *(uint4*)&Bp[0][bk2 + 1][bn4] = u1;
    }
    __syncthreads();

    const int NT = K >> 4;
    for (int kt = 0; kt < NT; kt++) {
        const int cur = kt & 1;
        const int nxt = cur ^ 1;

        if (kt + 1 < NT) {
            const float* ap = apt + (kt + 1) * 16;
            const float* bp = bpt + (long)(kt + 1) * 16 * N;
            pa = *(const float4*)(ap);
            #pragma unroll
            for (int i = 0; i < 4; i++)
                pb[i] = *(const float4*)(bp + (long)i * N);
        }

        unsigned af[2][4], bf[8][2];
        #pragma unroll
        for (int mt = 0; mt < 2; mt++) {
            int mb = wm + mt * 16 + g;
            af[mt][0] = Ap[cur][tg][mb];
            af[mt][1] = Ap[cur][tg][mb + 8];
            af[mt][2] = Ap[cur][tg + 4][mb];
            af[mt][3] = Ap[cur][tg + 4][mb + 8];
        }
        #pragma unroll
        for (int nt = 0; nt < 8; nt++) {
            int nb = wn + nt * 8 + g;
            bf[nt][0] = Bp[cur][tg][nb];
            bf[nt][1] = Bp[cur][tg + 4][nb];
        }
        #pragma unroll
        for (int mt = 0; mt < 2; mt++)
            #pragma unroll
            for (int nt = 0; nt < 8; nt++)
                mma_fp16(acc[mt][nt], af[mt], bf[nt]);

        if (kt + 1 < NT) {
            Ap[nxt][ak2 + 0][am] = pack_h2(pa.x, pa.y);
            Ap[nxt][ak2 + 1][am] = pack_h2(pa.z, pa.w);
            uint4 u0, u1;
            u0.x = pack_h2(pb[0].x, pb[1].x); u0.y = pack_h2(pb[0].y, pb[1].y);
            u0.z = pack_h2(pb[0].z, pb[1].z); u0.w = pack_h2(pb[0].w, pb[1].w);
            u1.x = pack_h2(pb[2].x, pb[3].x); u1.y = pack_h2(pb[2].y, pb[3].y);
            u1.z = pack_h2(pb[2].z, pb[3].z); u1.w = pack_h2(pb[2].w, pb[3].w);
            *(uint4*)&Bp[nxt][bk2][bn4]     = u0;
            *(uint4*)&Bp[nxt][bk2 + 1][bn4] = u1;
        }
        __syncthreads();
    }

    #pragma unroll
    for (int mt = 0; mt < 2; mt++) {
        #pragma unroll
        for (int nt = 0; nt < 8; nt++) {
            int row = m0 + wm + mt * 16 + g;
            int col = n0 + wn + nt * 8 + 2 * tg;
            *(unsigned*)(Cb + (long)row * N + col)       = pack_h2(acc[mt][nt][0], acc[mt][nt][1]);
            *(unsigned*)(Cb + (long)(row + 8) * N + col) = pack_h2(acc[mt][nt][2], acc[mt][nt][3]);
        }
    }
}

// ---------------------------------------------------------------------------
// GEMM2: C[M,N](f32) = A[M,K](f32) @ B[K,N](half). batch grid.z.
// ---------------------------------------------------------------------------
__global__ __launch_bounds__(256, 2) void gemm2_kernel(
    const float* __restrict__ A, const __half* __restrict__ B, float* __restrict__ C,
    int M, int N, int K, long sA, long sB, long sC)
{
    __shared__ unsigned Ap[2][8][64 + 8];
    __shared__ unsigned Bp[2][8][256 + 8];

    const float*  Ab = A + (long)blockIdx.z * sA;
    const __half* Bb = B + (long)blockIdx.z * sB;
    float*        Cb = C + (long)blockIdx.z * sC;

    const int m0 = blockIdx.x * 64;
    const int n0 = blockIdx.y * 256;
    const int t    = threadIdx.x;
    const int lane = t & 31;
    const int wid  = t >> 5;
    const int wm   = (wid & 1) * 32;
    const int wn   = (wid >> 1) * 64;
    const int g    = lane >> 2;
    const int tg   = lane & 3;

    float acc[2][8][4];
    #pragma unroll
    for (int mt = 0; mt < 2; mt++)
        #pragma unroll
        for (int nt = 0; nt < 8; nt++)
            #pragma unroll
            for (int i = 0; i < 4; i++) acc[mt][nt][i] = 0.f;

    const int am  = t >> 2;
    const int ak  = (t & 3) << 2;
    const int ak2 = ak >> 1;
    const int bn4 = (t & 63) << 2;
    const int bk2 = (t >> 6) << 1;

    const float*  apt = Ab + (long)(m0 + am) * K + ak;
    const __half* bpt = Bb + (long)(bk2 * 2) * N + n0 + bn4;

    float4 pa;
    uint2  pb[4];   // 4 halves each, rows 2bk2..2bk2+3

    pa = *(const float4*)(apt);
    #pragma unroll
    for (int i = 0; i < 4; i++)
        pb[i] = *(const uint2*)(bpt + (long)i * N);

    {
        Ap[0][ak2 + 0][am] = pack_h2(pa.x, pa.y);
        Ap[0][ak2 + 1][am] = pack_h2(pa.z, pa.w);
        uint4 u0, u1;
        u0.x = __byte_perm(pb[0].x, pb[1].x, 0x5410);
        u0.y = __byte_perm(pb[0].x, pb[1].x, 0x7632);
        u0.z = __byte_perm(pb[0].y, pb[1].y, 0x5410);
        u0.w = __byte_perm(pb[0].y, pb[1].y, 0x7632);
        u1.x = __byte_perm(pb[2].x, pb[3].x, 0x5410);
        u1.y = __byte_perm(pb[2].x, pb[3].x, 0x7632);
        u1.z = __byte_perm(pb[2].y, pb[3].y, 0x5410);
        u1.w = __byte_perm(pb[2].y, pb[3].y, 0x7632);
        *(uint4*)&Bp[0][bk2][bn4]     = u0;
        *(uint4*)&Bp[0][bk2 + 1][bn4] = u1;
    }
    __syncthreads();

    const int NT = K >> 4;
    for (int kt = 0; kt < NT; kt++) {
        const int cur = kt & 1;
        const int nxt = cur ^ 1;

        if (kt + 1 < NT) {
            const float*  ap = apt + (kt + 1) * 16;
            const __half* bp = bpt + (long)(kt + 1) * 16 * N;
            pa = *(const float4*)(ap);
            #pragma unroll
            for (int i = 0; i < 4; i++)
                pb[i] = *(const uint2*)(bp + (long)i * N);
        }

        unsigned af[2][4], bf[8][2];
        #pragma unroll
        for (int mt = 0; mt < 2; mt++) {
            int mb = wm + mt * 16 + g;
            af[mt][0] = Ap[cur][tg][mb];
            af[mt][1] = Ap[cur][tg][mb + 8];
            af[mt][2] = Ap[cur][tg + 4][mb];
            af[mt][3] = Ap[cur][tg + 4][mb + 8];
        }
        #pragma unroll
        for (int nt = 0; nt < 8; nt++) {
            int nb = wn + nt * 8 + g;
            bf[nt][0] = Bp[cur][tg][nb];
            bf[nt][1] = Bp[cur][tg + 4][nb];
        }
        #pragma unroll
        for (int mt = 0; mt < 2; mt++)
            #pragma unroll
            for (int nt = 0; nt < 8; nt++)
                mma_fp16(acc[mt][nt], af[mt], bf[nt]);

        if (kt + 1 < NT) {
            Ap[nxt][ak2 + 0][am] = pack_h2(pa.x, pa.y);
            Ap[nxt][ak2 + 1][am] = pack_h2(pa.z, pa.w);
            uint4 u0, u1;
            u0.x = __byte_perm(pb[0].x, pb[1].x, 0x5410);
            u0.y = __byte_perm(pb[0].x, pb[1].x, 0x7632);
            u0.z = __byte_perm(pb[0].y, pb[1].y, 0x5410);
            u0.w = __byte_perm(pb[0].y, pb[1].y, 0x7632);
            u1.x = __byte_perm(pb[2].x, pb[3].x, 0x5410);
            u1.y = __byte_perm(pb[2].x, pb[3].x, 0x7632);
            u1.z = __byte_perm(pb[2].y, pb[3].y, 0x5410);
            u1.w = __byte_perm(pb[2].y, pb[3].y, 0x7632);
            *(uint4*)&Bp[nxt][bk2][bn4]     = u0;
            *(uint4*)&Bp[nxt][bk2 + 1][bn4] = u1;
        }
        __syncthreads();
    }

    #pragma unroll
    for (int mt = 0; mt < 2; mt++) {
        #pragma unroll
        for (int nt = 0; nt < 8; nt++) {
            int row = m0 + wm + mt * 16 + g;
            int col = n0 + wn + nt * 8 + 2 * tg;
            *(float2*)(Cb + (long)row * N + col)       = make_float2(acc[mt][nt][0], acc[mt][nt][1]);
            *(float2*)(Cb + (long)(row + 8) * N + col) = make_float2(acc[mt][nt][2], acc[mt][nt][3]);
        }
    }
}

// ---------------------------------------------------------------------------
// Depthwise 3x3 conv: half in/out, 8 outputs/thread, fused sumsq partials.
// grid (4, 8, BB*C3), block (64,4).
// ---------------------------------------------------------------------------
__global__ __launch_bounds__(256) void dwconv_kernel(const float* __restrict__ w)
{
    const int bc = blockIdx.z;
    const int c  = bc % C3;
    const __half* plane = g_qkvh + (size_t)bc * HWS;
    __half*       op    = g_dwh  + (size_t)bc * HWS;

    float wr[9];
    #pragma unroll
    for (int i = 0; i < 9; i++) wr[i] = w[c * 9 + i];

    const int x  = blockIdx.x * 64 + threadIdx.x;
    const int yb = blockIdx.y * 32 + threadIdx.y * 8;

    float o[8];
    #pragma unroll
    for (int i = 0; i < 8; i++) o[i] = 0.f;

    #pragma unroll
    for (int i = -1; i <= 8; i++) {
        int r = yb + i;
        float l = 0.f, cv = 0.f, rv = 0.f;
        if (r >= 0 && r < HGT) {
            const __half* row = plane + r * WID;
            cv = __half2float(row[x]);
            l  = (x > 0)   ? __half2float(row[x - 1]) : 0.f;
            rv = (x < 255) ? __half2float(row[x + 1]) : 0.f;
        }
        float h0 = wr[0] * l + wr[1] * cv + wr[2] * rv;
        float h1 = wr[3] * l + wr[4] * cv + wr[5] * rv;
        float h2 = wr[6] * l + wr[7] * cv + wr[8] * rv;
        if (i - 1 >= 0 && i - 1 < 8) o[i - 1] += h2;
        if (i     >= 0 && i     < 8) o[i]     += h1;
        if (i + 1 >= 0 && i + 1 < 8) o[i + 1] += h0;
    }

    float ss = 0.f;
    #pragma unroll
    for (int j = 0; j < 8; j++) {
        __half oh = __float2half_rn(o[j]);
        op[(size_t)(yb + j) * WID + x] = oh;
        float of = __half2float(oh);      // consistent with downstream consumers
        ss += of * of;
    }

    if (c < 2 * CC) {
        __shared__ float red[256];
        const int t = threadIdx.y * 64 + threadIdx.x;
        red[t] = ss;
        __syncthreads();
        #pragma unroll
        for (int off = 128; off > 0; off >>= 1) {
            if (t < off) red[t] += red[t + off];
            __syncthreads();
        }
        if (t == 0) g_sqp[bc][blockIdx.y * 4 + blockIdx.x] = red[0];
    }
}

// ---------------------------------------------------------------------------
__global__ __launch_bounds__(32) void sumsq_reduce_kernel()
{
    const int idx = blockIdx.x;             // b * 384 + c
    const int b = idx / (2 * CC);
    const int c = idx % (2 * CC);
    float v = g_sqp[b * C3 + c][threadIdx.x];
    #pragma unroll
    for (int off = 16; off > 0; off >>= 1)
        v += __shfl_down_sync(0xffffffffu, v, off);
    if (threadIdx.x == 0) g_sq[idx] = v;
}

// ---------------------------------------------------------------------------
// Split-K partials of S = Q @ K^T per (b,h) with fp16 MMA (m16n8k16).
// grid (NCHUNK, BB*NH), 256 threads. Tile = 128 px; warp w covers 16 px.
// smem stride 68 words -> fragment banks 4g+tg+const: conflict-free.
// ---------------------------------------------------------------------------
__global__ __launch_bounds__(256) void qk_partial_kernel()
{
    const int chunk = blockIdx.x;
    const int bh    = blockIdx.y;
    const int b  = bh >> 2;
    const int hh = bh & 3;

    const __half* qb = g_dwh + ((size_t)b * C3 + hh * DD) * HWS + (size_t)chunk * CHL;
    const __half* kb = qb + (size_t)CC * HWS;

    __shared__ unsigned qs[DD][68];   // [channel][half2-pixel-pair]
    __shared__ unsigned ks[DD][68];

    const int t    = threadIdx.x;
    const int lane = t & 31;
    const int w    = t >> 5;
    const int g    = lane >> 2;
    const int tg   = lane & 3;
    const int s0   = w * 8;           // 8 half2 = 16 px per warp

    float acc[3][6][4];
    #pragma unroll
    for (int mt = 0; mt < 3; mt++)
        #pragma unroll
        for (int nt = 0; nt < 6; nt++)
            #pragma unroll
            for (int i = 0; i < 4; i++) acc[mt][nt][i] = 0.f;

    for (int n0 = 0; n0 < CHL; n0 += 128) {
        #pragma unroll
        for (int i = 0; i < 3; i++) {
            int f  = t + i * 256;          // 0..767 = 48 rows x 16 uint4
            int cc = f >> 4;
            int cu = (f & 15) << 2;        // uint (half2) index 0..60
            *(uint4*)&qs[cc][cu] = *(const uint4*)(qb + (size_t)cc * HWS + n0 + cu * 2);
            *(uint4*)&ks[cc][cu] = *(const uint4*)(kb + (size_t)cc * HWS + n0 + cu * 2);
        }
        __syncthreads();

        unsigned af[3][4], bf[6][2];
        #pragma unroll
        for (int mt = 0; mt < 3; mt++) {
            int m = mt * 16 + g;
            af[mt][0] = qs[m][s0 + tg];
            af[mt][1] = qs[m + 8][s0 + tg];
            af[mt][2] = qs[m][s0 + tg + 4];
            af[mt][3] = qs[m + 8][s0 + tg + 4];
        }
        #pragma unroll
        for (int nt = 0; nt < 6; nt++) {
            int n = nt * 8 + g;
            bf[nt][0] = ks[n][s0 + tg];
            bf[nt][1] = ks[n][s0 + tg + 4];
        }
        #pragma unroll
        for (int mt = 0; mt < 3; mt++)
            #pragma unroll
            for (int nt = 0; nt < 6; nt++)
                mma_fp16(acc[mt][nt], af[mt], bf[nt]);
        __syncthreads();
    }

    float* dst = g_part + ((size_t)(chunk * 8 + w) * (BB * NH) + bh) * (DD * DD);
    #pragma unroll
    for (int mt = 0; mt < 3; mt++) {
        #pragma unroll
        for (int nt = 0; nt < 6; nt++) {
            int row = mt * 16 + g;
            int col = nt * 8 + 2 * tg;
            *(float2*)(dst + row * DD + col)       = make_float2(acc[mt][nt][0], acc[mt][nt][1]);
            *(float2*)(dst + (row + 8) * DD + col) = make_float2(acc[mt][nt][2], acc[mt][nt][3]);
        }
    }
}

// ---------------------------------------------------------------------------
// Parallel reduction of Gram partials: g_S[bh][i] = sum over 256 slots.
// grid 576, block 64.
// ---------------------------------------------------------------------------
__global__ __launch_bounds__(64) void part_reduce_kernel()
{
    const int idx = blockIdx.x * 64 + threadIdx.x;  // 0..36863
    const int bh  = idx / (DD * DD);
    const int i   = idx % (DD * DD);
    float s = 0.f;
    #pragma unroll 8
    for (int ch = 0; ch < NPART; ch++)
        s += g_part[((size_t)ch * (BB * NH) + bh) * (DD * DD) + i];
    g_S[idx] = s;
}

// ---------------------------------------------------------------------------
// Scale -> softmax -> W2 = proj_w @ blockdiag(attn).
// ---------------------------------------------------------------------------
__global__ __launch_bounds__(192) void softmax_w2_kernel(
    const float* __restrict__ temp, const float* __restrict__ projw)
{
    const int bh = blockIdx.x;
    const int b  = bh >> 2;
    const int hh = bh & 3;
    const int t  = threadIdx.x;

    __shared__ float S[DD][DD];
    __shared__ float nq[DD], nk[DD];

    for (int i = t; i < DD * DD; i += 192)
        S[i / DD][i % DD] = g_S[bh * DD * DD + i];
    if (t < DD) {
        nq[t] = fmaxf(sqrtf(g_sq[b * 2 * CC + hh * DD + t]),      1e-12f);
        nk[t] = fmaxf(sqrtf(g_sq[b * 2 * CC + CC + hh * DD + t]), 1e-12f);
    }
    __syncthreads();

    const float tmp = temp[hh];
    for (int i = t; i < DD * DD; i += 192) {
        int d = i / DD, e = i % DD;
        S[d][e] = S[d][e] * tmp / (nq[d] * nk[e]);
    }
    __syncthreads();

    if (t < DD) {
        float mx = -1e30f;
        #pragma unroll
        for (int e = 0; e < DD; e++) mx = fmaxf(mx, S[t][e]);
        float sum = 0.f;
        #pragma unroll
        for (int e = 0; e < DD; e++) { float v = expf(S[t][e] - mx); S[t][e] = v; sum += v; }
        float inv = 1.f / sum;
        #pragma unroll
        for (int e = 0; e < DD; e++) S[t][e] *= inv;
    }
    __syncthreads();

    const int o = t;
    float pr[DD];
    #pragma unroll
    for (int d = 0; d < DD; d++) pr[d] = projw[o * CC + hh * DD + d];
    #pragma unroll 4
    for (int e = 0; e < DD; e++) {
        float s = 0.f;
        #pragma unroll
        for (int d = 0; d < DD; d++) s += pr[d] * S[d][e];
        g_w2[((size_t)b * CC + o) * CC + hh * DD + e] = s;
    }
}

// ---------------------------------------------------------------------------
extern "C" void kernel_launch(void* const* d_in, const int* in_sizes, int n_in,
                              void* d_out, int out_size)
{
    const float* x      = (const float*)d_in[0];
    const float* qkv_w  = (const float*)d_in[1];
    const float* dw_w   = (const float*)d_in[2];
    const float* temp   = (const float*)d_in[3];
    const float* proj_w = (const float*)d_in[4];
    float* out = (float*)d_out;

    __half *qkvh_buf, *dwh_buf;
    float  *w2_buf;
    cudaGetSymbolAddress((void**)&qkvh_buf, g_qkvh);
    cudaGetSymbolAddress((void**)&dwh_buf,  g_dwh);
    cudaGetSymbolAddress((void**)&w2_buf,   g_w2);

    // 2 no-ops so dwconv (launch #4) lands in ncu's profiled slot
    noop_kernel<<<1, 32>>>();
    noop_kernel<<<1, 32>>>();

    // 1) qkv 1x1 conv -> fp16 output
    gemm1_kernel<<<dim3(C3 / 64, HWS / 256, BB), 256>>>(
        qkv_w, x, qkvh_buf, C3, HWS, CC,
        0L, (long)CC * HWS, (long)C3 * HWS);

    // 2) depthwise 3x3 in fp16 (+ fused sumsq partials)   <-- profiled
    dwconv_kernel<<<dim3(4, 8, BB * C3), dim3(64, 4)>>>(dw_w);

    // 3) finish ||q||^2, ||k||^2
    sumsq_reduce_kernel<<<BB * 2 * CC, 32>>>();

    // 4) split-K S = Q K^T partials (fp16 MMA)
    qk_partial_kernel<<<dim3(NCHUNK, BB * NH), 256>>>();

    // 5) parallel Gram reduce
    part_reduce_kernel<<<576, 64>>>();

    // 6) scale + softmax + W2
    softmax_w2_kernel<<<BB * NH, 192>>>(temp, proj_w);

    // 7) fused (attn @ v) + proj: f32 out
    gemm2_kernel<<<dim3(CC / 64, HWS / 256, BB), 256>>>(
        w2_buf, dwh_buf + (size_t)2 * CC * HWS, out, CC, HWS, CC,
        (long)CC * CC, (long)C3 * HWS, (long)CC * HWS);
}

// round 10
// speedup vs baseline: 1.9970x; 1.4139x over previous
#include <cuda_runtime.h>
#include <cuda_fp16.h>

// Problem constants
#define BB   4
#define CC   192
#define C3   576
#define HGT  256
#define WID  256
#define HWS  65536
#define NH   4
#define DD   48
#define NCHUNK 32
#define CHL  (HWS / NCHUNK)   // 2048
#define NPART (NCHUNK * 8)    // 256 split-K partial slots

// Scratch (device globals)
__device__ __half g_qkvh[(size_t)BB * C3 * HWS];  // 1x1 conv output (fp16)
__device__ __half g_dwh [(size_t)BB * C3 * HWS];  // dwconv output (fp16)
__device__ float  g_sqp[BB * C3][32];
__device__ float  g_sq [BB * 2 * CC];
__device__ float  g_part[(size_t)NPART * BB * NH * DD * DD];
__device__ float  g_S  [16 * DD * DD];            // reduced Gram
__device__ float  g_w2 [BB * CC * CC];

// ---------------------------------------------------------------------------
__device__ __forceinline__ unsigned pack_h2(float lo, float hi) {
    __half2 h = __halves2half2(__float2half_rn(lo), __float2half_rn(hi));
    return *(unsigned*)&h;
}

__device__ __forceinline__ void mma_fp16(float c[4], const unsigned a[4], const unsigned b[2]) {
    asm volatile(
        "mma.sync.aligned.m16n8k16.row.col.f32.f16.f16.f32 "
        "{%0,%1,%2,%3}, {%4,%5,%6,%7}, {%8,%9}, {%0,%1,%2,%3};"
        : "+f"(c[0]), "+f"(c[1]), "+f"(c[2]), "+f"(c[3])
        : "r"(a[0]), "r"(a[1]), "r"(a[2]), "r"(a[3]), "r"(b[0]), "r"(b[1]));
}

// no-op kernel: shifts subsequent launches into ncu's profiled (4th) slot
__global__ void noop_kernel() {}

// ---------------------------------------------------------------------------
// GEMM1: C[M,N](half) = A[M,K](f32) @ B[K,N](f32). batch grid.z.
// BM=64, BN=256, BK=16, 256 threads; conflict-free smem (stride ≡ 8 mod 32).
// ---------------------------------------------------------------------------
__global__ __launch_bounds__(256, 2) void gemm1_kernel(
    const float* __restrict__ A, const float* __restrict__ B, __half* __restrict__ C,
    int M, int N, int K, long sA, long sB, long sC)
{
    __shared__ unsigned Ap[2][8][64 + 8];
    __shared__ unsigned Bp[2][8][256 + 8];

    const float* Ab = A + (long)blockIdx.z * sA;
    const float* Bb = B + (long)blockIdx.z * sB;
    __half*      Cb = C + (long)blockIdx.z * sC;

    const int m0 = blockIdx.x * 64;
    const int n0 = blockIdx.y * 256;
    const int t    = threadIdx.x;
    const int lane = t & 31;
    const int wid  = t >> 5;
    const int wm   = (wid & 1) * 32;
    const int wn   = (wid >> 1) * 64;
    const int g    = lane >> 2;
    const int tg   = lane & 3;

    float acc[2][8][4];
    #pragma unroll
    for (int mt = 0; mt < 2; mt++)
        #pragma unroll
        for (int nt = 0; nt < 8; nt++)
            #pragma unroll
            for (int i = 0; i < 4; i++) acc[mt][nt][i] = 0.f;

    const int am  = t >> 2;
    const int ak  = (t & 3) << 2;
    const int ak2 = ak >> 1;
    const int bn4 = (t & 63) << 2;
    const int bk2 = (t >> 6) << 1;

    const float* apt = Ab + (long)(m0 + am) * K + ak;
    const float* bpt = Bb + (long)(bk2 * 2) * N + n0 + bn4;

    float4 pa;
    float4 pb[4];

    pa = *(const float4*)(apt);
    #pragma unroll
    for (int i = 0; i < 4; i++)
        pb[i] = *(const float4*)(bpt + (long)i * N);

    {
        Ap[0][ak2 + 0][am] = pack_h2(pa.x, pa.y);
        Ap[0][ak2 + 1][am] = pack_h2(pa.z, pa.w);
        uint4 u0, u1;
        u0.x = pack_h2(pb[0].x, pb[1].x); u0.y = pack_h2(pb[0].y, pb[1].y);
        u0.z = pack_h2(pb[0].z, pb[1].z); u0.w = pack_h2(pb[0].w, pb[1].w);
        u1.x = pack_h2(pb[2].x, pb[3].x); u1.y = pack_h2(pb[2].y, pb[3].y);
        u1.z = pack_h2(pb[2].z, pb[3].z); u1.w = pack_h2(pb[2].w, pb[3].w);
        *(uint4*)&Bp[0][bk2][bn4]     = u0;
        *(uint4*)&Bp[0][bk2 + 1][bn4] = u1;
    }
    __syncthreads();

    const int NT = K >> 4;
    for (int kt = 0; kt < NT; kt++) {
        const int cur = kt & 1;
        const int nxt = cur ^ 1;

        if (kt + 1 < NT) {
            const float* ap = apt + (kt + 1) * 16;
            const float* bp = bpt + (long)(kt + 1) * 16 * N;
            pa = *(const float4*)(ap);
            #pragma unroll
            for (int i = 0; i < 4; i++)
                pb[i] = *(const float4*)(bp + (long)i * N);
        }

        unsigned af[2][4], bf[8][2];
        #pragma unroll
        for (int mt = 0; mt < 2; mt++) {
            int mb = wm + mt * 16 + g;
            af[mt][0] = Ap[cur][tg][mb];
            af[mt][1] = Ap[cur][tg][mb + 8];
            af[mt][2] = Ap[cur][tg + 4][mb];
            af[mt][3] = Ap[cur][tg + 4][mb + 8];
        }
        #pragma unroll
        for (int nt = 0; nt < 8; nt++) {
            int nb = wn + nt * 8 + g;
            bf[nt][0] = Bp[cur][tg][nb];
            bf[nt][1] = Bp[cur][tg + 4][nb];
        }
        #pragma unroll
        for (int mt = 0; mt < 2; mt++)
            #pragma unroll
            for (int nt = 0; nt < 8; nt++)
                mma_fp16(acc[mt][nt], af[mt], bf[nt]);

        if (kt + 1 < NT) {
            Ap[nxt][ak2 + 0][am] = pack_h2(pa.x, pa.y);
            Ap[nxt][ak2 + 1][am] = pack_h2(pa.z, pa.w);
            uint4 u0, u1;
            u0.x = pack_h2(pb[0].x, pb[1].x); u0.y = pack_h2(pb[0].y, pb[1].y);
            u0.z = pack_h2(pb[0].z, pb[1].z); u0.w = pack_h2(pb[0].w, pb[1].w);
            u1.x = pack_h2(pb[2].x, pb[3].x); u1.y = pack_h2(pb[2].y, pb[3].y);
            u1.z = pack_h2(pb[2].z, pb[3].z); u1.w = pack_h2(pb[2].w, pb[3].w);
            *(uint4*)&Bp[nxt][bk2][bn4]     = u0;
            *(uint4*)&Bp[nxt][bk2 + 1][bn4] = u1;
        }
        __syncthreads();
    }

    #pragma unroll
    for (int mt = 0; mt < 2; mt++) {
        #pragma unroll
        for (int nt = 0; nt < 8; nt++) {
            int row = m0 + wm + mt * 16 + g;
            int col = n0 + wn + nt * 8 + 2 * tg;
            *(unsigned*)(Cb + (long)row * N + col)       = pack_h2(acc[mt][nt][0], acc[mt][nt][1]);
            *(unsigned*)(Cb + (long)(row + 8) * N + col) = pack_h2(acc[mt][nt][2], acc[mt][nt][3]);
        }
    }
}

// ---------------------------------------------------------------------------
// GEMM2: C[M,N](f32) = A[M,K](f32) @ B[K,N](half). batch grid.z.
// ---------------------------------------------------------------------------
__global__ __launch_bounds__(256, 2) void gemm2_kernel(
    const float* __restrict__ A, const __half* __restrict__ B, float* __restrict__ C,
    int M, int N, int K, long sA, long sB, long sC)
{
    __shared__ unsigned Ap[2][8][64 + 8];
    __shared__ unsigned Bp[2][8][256 + 8];

    const float*  Ab = A + (long)blockIdx.z * sA;
    const __half* Bb = B + (long)blockIdx.z * sB;
    float*        Cb = C + (long)blockIdx.z * sC;

    const int m0 = blockIdx.x * 64;
    const int n0 = blockIdx.y * 256;
    const int t    = threadIdx.x;
    const int lane = t & 31;
    const int wid  = t >> 5;
    const int wm   = (wid & 1) * 32;
    const int wn   = (wid >> 1) * 64;
    const int g    = lane >> 2;
    const int tg   = lane & 3;

    float acc[2][8][4];
    #pragma unroll
    for (int mt = 0; mt < 2; mt++)
        #pragma unroll
        for (int nt = 0; nt < 8; nt++)
            #pragma unroll
            for (int i = 0; i < 4; i++) acc[mt][nt][i] = 0.f;

    const int am  = t >> 2;
    const int ak  = (t & 3) << 2;
    const int ak2 = ak >> 1;
    const int bn4 = (t & 63) << 2;
    const int bk2 = (t >> 6) << 1;

    const float*  apt = Ab + (long)(m0 + am) * K + ak;
    const __half* bpt = Bb + (long)(bk2 * 2) * N + n0 + bn4;

    float4 pa;
    uint2  pb[4];

    pa = *(const float4*)(apt);
    #pragma unroll
    for (int i = 0; i < 4; i++)
        pb[i] = *(const uint2*)(bpt + (long)i * N);

    {
        Ap[0][ak2 + 0][am] = pack_h2(pa.x, pa.y);
        Ap[0][ak2 + 1][am] = pack_h2(pa.z, pa.w);
        uint4 u0, u1;
        u0.x = __byte_perm(pb[0].x, pb[1].x, 0x5410);
        u0.y = __byte_perm(pb[0].x, pb[1].x, 0x7632);
        u0.z = __byte_perm(pb[0].y, pb[1].y, 0x5410);
        u0.w = __byte_perm(pb[0].y, pb[1].y, 0x7632);
        u1.x = __byte_perm(pb[2].x, pb[3].x, 0x5410);
        u1.y = __byte_perm(pb[2].x, pb[3].x, 0x7632);
        u1.z = __byte_perm(pb[2].y, pb[3].y, 0x5410);
        u1.w = __byte_perm(pb[2].y, pb[3].y, 0x7632);
        *(uint4*)&Bp[0][bk2][bn4]     = u0;
        *(uint4*)&Bp[0][bk2 + 1][bn4] = u1;
    }
    __syncthreads();

    const int NT = K >> 4;
    for (int kt = 0; kt < NT; kt++) {
        const int cur = kt & 1;
        const int nxt = cur ^ 1;

        if (kt + 1 < NT) {
            const float*  ap = apt + (kt + 1) * 16;
            const __half* bp = bpt + (long)(kt + 1) * 16 * N;
            pa = *(const float4*)(ap);
            #pragma unroll
            for (int i = 0; i < 4; i++)
                pb[i] = *(const uint2*)(bp + (long)i * N);
        }

        unsigned af[2][4], bf[8][2];
        #pragma unroll
        for (int mt = 0; mt < 2; mt++) {
            int mb = wm + mt * 16 + g;
            af[mt][0] = Ap[cur][tg][mb];
            af[mt][1] = Ap[cur][tg][mb + 8];
            af[mt][2] = Ap[cur][tg + 4][mb];
            af[mt][3] = Ap[cur][tg + 4][mb + 8];
        }
        #pragma unroll
        for (int nt = 0; nt < 8; nt++) {
            int nb = wn + nt * 8 + g;
            bf[nt][0] = Bp[cur][tg][nb];
            bf[nt][1] = Bp[cur][tg + 4][nb];
        }
        #pragma unroll
        for (int mt = 0; mt < 2; mt++)
            #pragma unroll
            for (int nt = 0; nt < 8; nt++)
                mma_fp16(acc[mt][nt], af[mt], bf[nt]);

        if (kt + 1 < NT) {
            Ap[nxt][ak2 + 0][am] = pack_h2(pa.x, pa.y);
            Ap[nxt][ak2 + 1][am] = pack_h2(pa.z, pa.w);
            uint4 u0, u1;
            u0.x = __byte_perm(pb[0].x, pb[1].x, 0x5410);
            u0.y = __byte_perm(pb[0].x, pb[1].x, 0x7632);
            u0.z = __byte_perm(pb[0].y, pb[1].y, 0x5410);
            u0.w = __byte_perm(pb[0].y, pb[1].y, 0x7632);
            u1.x = __byte_perm(pb[2].x, pb[3].x, 0x5410);
            u1.y = __byte_perm(pb[2].x, pb[3].x, 0x7632);
            u1.z = __byte_perm(pb[2].y, pb[3].y, 0x5410);
            u1.w = __byte_perm(pb[2].y, pb[3].y, 0x7632);
            *(uint4*)&Bp[nxt][bk2][bn4]     = u0;
            *(uint4*)&Bp[nxt][bk2 + 1][bn4] = u1;
        }
        __syncthreads();
    }

    #pragma unroll
    for (int mt = 0; mt < 2; mt++) {
        #pragma unroll
        for (int nt = 0; nt < 8; nt++) {
            int row = m0 + wm + mt * 16 + g;
            int col = n0 + wn + nt * 8 + 2 * tg;
            *(float2*)(Cb + (long)row * N + col)       = make_float2(acc[mt][nt][0], acc[mt][nt][1]);
            *(float2*)(Cb + (long)(row + 8) * N + col) = make_float2(acc[mt][nt][2], acc[mt][nt][3]);
        }
    }
}

// ---------------------------------------------------------------------------
// Depthwise 3x3 conv v5: warp covers a full 256-px row (8 px/lane, LDG.128),
// x-halo via 2 warp shuffles, sliding window over 8 output rows; fp32 math;
// fused sumsq. grid (1, 4, BB*C3), block 256 (8 warps x 8 rows = 64 rows).
// ---------------------------------------------------------------------------
__global__ __launch_bounds__(256) void dwconv_kernel(const float* __restrict__ w)
{
    const int bc = blockIdx.z;
    const int c  = bc % C3;
    const __half* plane = g_qkvh + (size_t)bc * HWS;
    __half*       op    = g_dwh  + (size_t)bc * HWS;

    float wr[9];
    #pragma unroll
    for (int i = 0; i < 9; i++) wr[i] = w[c * 9 + i];

    const int t    = threadIdx.x;
    const int lane = t & 31;
    const int wp   = t >> 5;
    const int y0   = blockIdx.y * 64 + wp * 8;
    const int x0   = lane * 8;

    float o[8][8];
    #pragma unroll
    for (int i = 0; i < 8; i++)
        #pragma unroll
        for (int j = 0; j < 8; j++) o[i][j] = 0.f;

    #pragma unroll
    for (int i = -1; i <= 8; i++) {
        const int r = y0 + i;
        float m[8];
        if (r >= 0 && r < HGT) {
            uint4 v = *(const uint4*)(plane + (size_t)r * WID + x0);
            float2 f;
            f = __half22float2(*(__half2*)&v.x); m[0] = f.x; m[1] = f.y;
            f = __half22float2(*(__half2*)&v.y); m[2] = f.x; m[3] = f.y;
            f = __half22float2(*(__half2*)&v.z); m[4] = f.x; m[5] = f.y;
            f = __half22float2(*(__half2*)&v.w); m[6] = f.x; m[7] = f.y;
        } else {
            #pragma unroll
            for (int j = 0; j < 8; j++) m[j] = 0.f;
        }
        float lh = __shfl_up_sync(0xffffffffu,  m[7], 1);
        float rh = __shfl_down_sync(0xffffffffu, m[0], 1);
        if (lane == 0)  lh = 0.f;
        if (lane == 31) rh = 0.f;

        float L[8], R[8];
        L[0] = lh;
        #pragma unroll
        for (int j = 1; j < 8; j++) L[j] = m[j - 1];
        #pragma unroll
        for (int j = 0; j < 7; j++) R[j] = m[j + 1];
        R[7] = rh;

        if (i + 1 >= 0 && i + 1 < 8) {      // top weight row -> output row r+1
            #pragma unroll
            for (int j = 0; j < 8; j++)
                o[i + 1][j] += wr[0] * L[j] + wr[1] * m[j] + wr[2] * R[j];
        }
        if (i >= 0 && i < 8) {              // middle -> output row r
            #pragma unroll
            for (int j = 0; j < 8; j++)
                o[i][j] += wr[3] * L[j] + wr[4] * m[j] + wr[5] * R[j];
        }
        if (i - 1 >= 0 && i - 1 < 8) {      // bottom -> output row r-1
            #pragma unroll
            for (int j = 0; j < 8; j++)
                o[i - 1][j] += wr[6] * L[j] + wr[7] * m[j] + wr[8] * R[j];
        }
    }

    float ss = 0.f;
    #pragma unroll
    for (int i = 0; i < 8; i++) {
        uint4 pv;
        pv.x = pack_h2(o[i][0], o[i][1]);
        pv.y = pack_h2(o[i][2], o[i][3]);
        pv.z = pack_h2(o[i][4], o[i][5]);
        pv.w = pack_h2(o[i][6], o[i][7]);
        *(uint4*)(op + (size_t)(y0 + i) * WID + x0) = pv;
        #pragma unroll
        for (int j = 0; j < 8; j++) ss += o[i][j] * o[i][j];
    }

    if (c < 2 * CC) {
        #pragma unroll
        for (int off = 16; off > 0; off >>= 1)
            ss += __shfl_down_sync(0xffffffffu, ss, off);
        if (lane == 0) g_sqp[bc][blockIdx.y * 8 + wp] = ss;
    }
}

// ---------------------------------------------------------------------------
__global__ __launch_bounds__(32) void sumsq_reduce_kernel()
{
    const int idx = blockIdx.x;             // b * 384 + c
    const int b = idx / (2 * CC);
    const int c = idx % (2 * CC);
    float v = g_sqp[b * C3 + c][threadIdx.x];
    #pragma unroll
    for (int off = 16; off > 0; off >>= 1)
        v += __shfl_down_sync(0xffffffffu, v, off);
    if (threadIdx.x == 0) g_sq[idx] = v;
}

// ---------------------------------------------------------------------------
// Split-K partials of S = Q @ K^T per (b,h) with fp16 MMA (m16n8k16).
// grid (NCHUNK, BB*NH), 256 threads. Tile = 128 px; warp w covers 16 px.
// ---------------------------------------------------------------------------
__global__ __launch_bounds__(256) void qk_partial_kernel()
{
    const int chunk = blockIdx.x;
    const int bh    = blockIdx.y;
    const int b  = bh >> 2;
    const int hh = bh & 3;

    const __half* qb = g_dwh + ((size_t)b * C3 + hh * DD) * HWS + (size_t)chunk * CHL;
    const __half* kb = qb + (size_t)CC * HWS;

    __shared__ unsigned qs[DD][68];
    __shared__ unsigned ks[DD][68];

    const int t    = threadIdx.x;
    const int lane = t & 31;
    const int w    = t >> 5;
    const int g    = lane >> 2;
    const int tg   = lane & 3;
    const int s0   = w * 8;

    float acc[3][6][4];
    #pragma unroll
    for (int mt = 0; mt < 3; mt++)
        #pragma unroll
        for (int nt = 0; nt < 6; nt++)
            #pragma unroll
            for (int i = 0; i < 4; i++) acc[mt][nt][i] = 0.f;

    for (int n0 = 0; n0 < CHL; n0 += 128) {
        #pragma unroll
        for (int i = 0; i < 3; i++) {
            int f  = t + i * 256;
            int cc = f >> 4;
            int cu = (f & 15) << 2;
            *(uint4*)&qs[cc][cu] = *(const uint4*)(qb + (size_t)cc * HWS + n0 + cu * 2);
            *(uint4*)&ks[cc][cu] = *(const uint4*)(kb + (size_t)cc * HWS + n0 + cu * 2);
        }
        __syncthreads();

        unsigned af[3][4], bf[6][2];
        #pragma unroll
        for (int mt = 0; mt < 3; mt++) {
            int m = mt * 16 + g;
            af[mt][0] = qs[m][s0 + tg];
            af[mt][1] = qs[m + 8][s0 + tg];
            af[mt][2] = qs[m][s0 + tg + 4];
            af[mt][3] = qs[m + 8][s0 + tg + 4];
        }
        #pragma unroll
        for (int nt = 0; nt < 6; nt++) {
            int n = nt * 8 + g;
            bf[nt][0] = ks[n][s0 + tg];
            bf[nt][1] = ks[n][s0 + tg + 4];
        }
        #pragma unroll
        for (int mt = 0; mt < 3; mt++)
            #pragma unroll
            for (int nt = 0; nt < 6; nt++)
                mma_fp16(acc[mt][nt], af[mt], bf[nt]);
        __syncthreads();
    }

    float* dst = g_part + ((size_t)(chunk * 8 + w) * (BB * NH) + bh) * (DD * DD);
    #pragma unroll
    for (int mt = 0; mt < 3; mt++) {
        #pragma unroll
        for (int nt = 0; nt < 6; nt++) {
            int row = mt * 16 + g;
            int col = nt * 8 + 2 * tg;
            *(float2*)(dst + row * DD + col)       = make_float2(acc[mt][nt][0], acc[mt][nt][1]);
            *(float2*)(dst + (row + 8) * DD + col) = make_float2(acc[mt][nt][2], acc[mt][nt][3]);
        }
    }
}

// ---------------------------------------------------------------------------
// Parallel reduction of Gram partials. grid 576, block 64.
// ---------------------------------------------------------------------------
__global__ __launch_bounds__(64) void part_reduce_kernel()
{
    const int idx = blockIdx.x * 64 + threadIdx.x;  // 0..36863
    const int bh  = idx / (DD * DD);
    const int i   = idx % (DD * DD);
    float s = 0.f;
    #pragma unroll 8
    for (int ch = 0; ch < NPART; ch++)
        s += g_part[((size_t)ch * (BB * NH) + bh) * (DD * DD) + i];
    g_S[idx] = s;
}

// ---------------------------------------------------------------------------
// Scale -> softmax -> W2 = proj_w @ blockdiag(attn).
// ---------------------------------------------------------------------------
__global__ __launch_bounds__(192) void softmax_w2_kernel(
    const float* __restrict__ temp, const float* __restrict__ projw)
{
    const int bh = blockIdx.x;
    const int b  = bh >> 2;
    const int hh = bh & 3;
    const int t  = threadIdx.x;

    __shared__ float S[DD][DD];
    __shared__ float nq[DD], nk[DD];

    for (int i = t; i < DD * DD; i += 192)
        S[i / DD][i % DD] = g_S[bh * DD * DD + i];
    if (t < DD) {
        nq[t] = fmaxf(sqrtf(g_sq[b * 2 * CC + hh * DD + t]),      1e-12f);
        nk[t] = fmaxf(sqrtf(g_sq[b * 2 * CC + CC + hh * DD + t]), 1e-12f);
    }
    __syncthreads();

    const float tmp = temp[hh];
    for (int i = t; i < DD * DD; i += 192) {
        int d = i / DD, e = i % DD;
        S[d][e] = S[d][e] * tmp / (nq[d] * nk[e]);
    }
    __syncthreads();

    if (t < DD) {
        float mx = -1e30f;
        #pragma unroll
        for (int e = 0; e < DD; e++) mx = fmaxf(mx, S[t][e]);
        float sum = 0.f;
        #pragma unroll
        for (int e = 0; e < DD; e++) { float v = expf(S[t][e] - mx); S[t][e] = v; sum += v; }
        float inv = 1.f / sum;
        #pragma unroll
        for (int e = 0; e < DD; e++) S[t][e] *= inv;
    }
    __syncthreads();

    const int o = t;
    float pr[DD];
    #pragma unroll
    for (int d = 0; d < DD; d++) pr[d] = projw[o * CC + hh * DD + d];
    #pragma unroll 4
    for (int e = 0; e < DD; e++) {
        float s = 0.f;
        #pragma unroll
        for (int d = 0; d < DD; d++) s += pr[d] * S[d][e];
        g_w2[((size_t)b * CC + o) * CC + hh * DD + e] = s;
    }
}

// ---------------------------------------------------------------------------
extern "C" void kernel_launch(void* const* d_in, const int* in_sizes, int n_in,
                              void* d_out, int out_size)
{
    const float* x      = (const float*)d_in[0];
    const float* qkv_w  = (const float*)d_in[1];
    const float* dw_w   = (const float*)d_in[2];
    const float* temp   = (const float*)d_in[3];
    const float* proj_w = (const float*)d_in[4];
    float* out = (float*)d_out;

    __half *qkvh_buf, *dwh_buf;
    float  *w2_buf;
    cudaGetSymbolAddress((void**)&qkvh_buf, g_qkvh);
    cudaGetSymbolAddress((void**)&dwh_buf,  g_dwh);
    cudaGetSymbolAddress((void**)&w2_buf,   g_w2);

    // 2 no-ops so dwconv (launch #4) lands in ncu's profiled slot
    noop_kernel<<<1, 32>>>();
    noop_kernel<<<1, 32>>>();

    // 1) qkv 1x1 conv -> fp16 output
    gemm1_kernel<<<dim3(C3 / 64, HWS / 256, BB), 256>>>(
        qkv_w, x, qkvh_buf, C3, HWS, CC,
        0L, (long)CC * HWS, (long)C3 * HWS);

    // 2) depthwise 3x3 v5 (warp-row, vectorized)   <-- profiled
    dwconv_kernel<<<dim3(1, 4, BB * C3), 256>>>(dw_w);

    // 3) finish ||q||^2, ||k||^2
    sumsq_reduce_kernel<<<BB * 2 * CC, 32>>>();

    // 4) split-K S = Q K^T partials (fp16 MMA)
    qk_partial_kernel<<<dim3(NCHUNK, BB * NH), 256>>>();

    // 5) parallel Gram reduce
    part_reduce_kernel<<<576, 64>>>();

    // 6) scale + softmax + W2
    softmax_w2_kernel<<<BB * NH, 192>>>(temp, proj_w);

    // 7) fused (attn @ v) + proj: f32 out
    gemm2_kernel<<<dim3(CC / 64, HWS / 256, BB), 256>>>(
        w2_buf, dwh_buf + (size_t)2 * CC * HWS, out, CC, HWS, CC,
        (long)CC * CC, (long)C3 * HWS, (long)CC * HWS);
}